// round 1
// baseline (speedup 1.0000x reference)
#include <cuda_runtime.h>
#include <cuda_bf16.h>
#include <math.h>
#include <stdint.h>

// Shapes: x (16, 256, 64, 64, 4) f32, comp_w (4,1,256), comp_b (4,1),
// exc_w (4,256,1), exc_b (4,256). Output same shape as x.
// B*C = 4096 (b,c) groups; each group has 64*64 = 4096 float4 (comp innermost).

#define NB 16
#define NC 256
#define SP 4096              // 64*64 spatial positions per (b,c)
#define NBC (NB * NC)        // 4096
#define N4 ((int64_t)NBC * SP)  // 16,777,216 float4 elements

__device__ float4 g_pooled[NBC];  // (b*C + c) -> per-component max
__device__ float4 g_u[NBC];       // (b*C + c) -> per-component scale

// ---------------------------------------------------------------------------
// K1: per-(b,c) spatial max pool. One block per (b,c), 256 threads.
// ---------------------------------------------------------------------------
__global__ void __launch_bounds__(256) pool_kernel(const float* __restrict__ x) {
    const int bc = blockIdx.x;
    const float4* xp = reinterpret_cast<const float4*>(x) + (size_t)bc * SP;

    float4 m = make_float4(-INFINITY, -INFINITY, -INFINITY, -INFINITY);
    #pragma unroll 4
    for (int i = threadIdx.x; i < SP; i += 256) {
        float4 v = xp[i];
        m.x = fmaxf(m.x, v.x);
        m.y = fmaxf(m.y, v.y);
        m.z = fmaxf(m.z, v.z);
        m.w = fmaxf(m.w, v.w);
    }
    // warp reduce
    #pragma unroll
    for (int o = 16; o > 0; o >>= 1) {
        m.x = fmaxf(m.x, __shfl_xor_sync(0xffffffffu, m.x, o));
        m.y = fmaxf(m.y, __shfl_xor_sync(0xffffffffu, m.y, o));
        m.z = fmaxf(m.z, __shfl_xor_sync(0xffffffffu, m.z, o));
        m.w = fmaxf(m.w, __shfl_xor_sync(0xffffffffu, m.w, o));
    }
    __shared__ float4 sm[8];
    const int lane = threadIdx.x & 31;
    const int warp = threadIdx.x >> 5;
    if (lane == 0) sm[warp] = m;
    __syncthreads();
    if (threadIdx.x == 0) {
        float4 r = sm[0];
        #pragma unroll
        for (int w = 1; w < 8; w++) {
            r.x = fmaxf(r.x, sm[w].x);
            r.y = fmaxf(r.y, sm[w].y);
            r.z = fmaxf(r.z, sm[w].z);
            r.w = fmaxf(r.w, sm[w].w);
        }
        g_pooled[bc] = r;
    }
}

// ---------------------------------------------------------------------------
// K2: per-batch squeeze (256 -> 1) + excite (1 -> 256). 16 blocks x 256 thr.
// qlinear semantics:
//   comps[o][c] = sum_i x[i][c] * W[c][o][i] + b[c][o]
//   out = { r+x+y+z, x-r-z+y, y+z-r-x, z-y+x-r } with (r,x,y,z)=comps[..0..3]
// ---------------------------------------------------------------------------
__global__ void __launch_bounds__(256) excite_kernel(const float* __restrict__ comp_w,
                                                     const float* __restrict__ comp_b,
                                                     const float* __restrict__ exc_w,
                                                     const float* __restrict__ exc_b) {
    const int b = blockIdx.x;
    const int t = threadIdx.x;  // channel index 0..255
    const int lane = t & 31;
    const int warp = t >> 5;

    float4 p = g_pooled[b * NC + t];
    // comp_w layout (4,1,256): comp_w[c*256 + i]
    float s0 = p.x * comp_w[0 * NC + t];
    float s1 = p.y * comp_w[1 * NC + t];
    float s2 = p.z * comp_w[2 * NC + t];
    float s3 = p.w * comp_w[3 * NC + t];

    #pragma unroll
    for (int o = 16; o > 0; o >>= 1) {
        s0 += __shfl_xor_sync(0xffffffffu, s0, o);
        s1 += __shfl_xor_sync(0xffffffffu, s1, o);
        s2 += __shfl_xor_sync(0xffffffffu, s2, o);
        s3 += __shfl_xor_sync(0xffffffffu, s3, o);
    }
    __shared__ float4 sm[8];
    __shared__ float4 u1s;
    if (lane == 0) sm[warp] = make_float4(s0, s1, s2, s3);
    __syncthreads();
    if (t == 0) {
        // comp_b layout (4,1): comp_b[c]
        float r  = comp_b[0];
        float xc = comp_b[1];
        float yc = comp_b[2];
        float zc = comp_b[3];
        #pragma unroll
        for (int w = 0; w < 8; w++) {
            r  += sm[w].x;
            xc += sm[w].y;
            yc += sm[w].z;
            zc += sm[w].w;
        }
        u1s = make_float4(r + xc + yc + zc,
                          xc - r - zc + yc,
                          yc + zc - r - xc,
                          zc - yc + xc - r);
    }
    __syncthreads();
    float4 u1 = u1s;

    // exc_w layout (4,256,1): exc_w[c*256 + o]; exc_b (4,256): exc_b[c*256 + o]
    float r2 = u1.x * exc_w[0 * NC + t] + exc_b[0 * NC + t];
    float x2 = u1.y * exc_w[1 * NC + t] + exc_b[1 * NC + t];
    float y2 = u1.z * exc_w[2 * NC + t] + exc_b[2 * NC + t];
    float z2 = u1.w * exc_w[3 * NC + t] + exc_b[3 * NC + t];

    g_u[b * NC + t] = make_float4(r2 + x2 + y2 + z2,
                                  x2 - r2 - z2 + y2,
                                  y2 + z2 - r2 - x2,
                                  z2 - y2 + x2 - r2);
}

// ---------------------------------------------------------------------------
// K3: out = x * u[b,c] broadcast over spatial. Grid-stride float4.
// ---------------------------------------------------------------------------
__global__ void __launch_bounds__(256) scale_kernel(const float* __restrict__ x,
                                                    float* __restrict__ out) {
    const float4* xp = reinterpret_cast<const float4*>(x);
    float4* op = reinterpret_cast<float4*>(out);
    int64_t stride = (int64_t)gridDim.x * blockDim.x;
    for (int64_t i = (int64_t)blockIdx.x * blockDim.x + threadIdx.x; i < N4; i += stride) {
        int bc = (int)(i >> 12);  // 4096 float4s per (b,c)
        float4 u = g_u[bc];
        float4 v = xp[i];
        op[i] = make_float4(v.x * u.x, v.y * u.y, v.z * u.z, v.w * u.w);
    }
}

extern "C" void kernel_launch(void* const* d_in, const int* in_sizes, int n_in,
                              void* d_out, int out_size) {
    const float* x      = (const float*)d_in[0];
    const float* comp_w = (const float*)d_in[1];
    const float* comp_b = (const float*)d_in[2];
    const float* exc_w  = (const float*)d_in[3];
    const float* exc_b  = (const float*)d_in[4];
    float* out = (float*)d_out;

    pool_kernel<<<NBC, 256>>>(x);
    excite_kernel<<<NB, 256>>>(comp_w, comp_b, exc_w, exc_b);
    scale_kernel<<<8192, 256>>>(x, out);
}